// round 13
// baseline (speedup 1.0000x reference)
#include <cuda_runtime.h>
#include <math.h>

#define NG 1024
#define NV 2
#define HW 128
#define NROW 16
#define NT 256            // 16x16 tiles of 8x8 px
#define SH_C0 0.28209479177387814f
#define SH_C1 0.4886025119029199f

typedef unsigned long long u64;
#define U64MAX 0xFFFFFFFFFFFFFFFFull

// Per-gaussian payload in ORIGINAL index order:
// A = (u, v, conic_a, conic_b); B = (conic_c, opacity, colR, colG); b = colB
// BZ.x = packed tile bbox (tx0|tx1<<8|ty0<<16|ty1<<24), BZ.y = camera-z bits
__device__ float4 d_A[NV][NG], d_B[NV][NG];
__device__ float  d_b[NV][NG];
__device__ uint2  d_BZ[NV][NG];
// Per-row depth-sorted lists. key = zbits<<18 | idx<<8 | tx0<<4 | tx1
__device__ int d_rowCnt[NV][NROW];
__device__ u64 d_rowList[NV][NROW][NG];

__global__ __launch_bounds__(128)
void project_kernel(const float* __restrict__ xyz,
                    const float* __restrict__ feats,
                    const float* __restrict__ scal,
                    const float* __restrict__ rot,
                    const float* __restrict__ opac,
                    const float* __restrict__ C2W,
                    const float* __restrict__ intr)
{
    const int v = blockIdx.y;
    const int i = blockIdx.x * 128 + threadIdx.x;

    const float* M = C2W + v * 16;
    const float Rc00 = M[0], Rc01 = M[4], Rc02 = M[8];
    const float Rc10 = M[1], Rc11 = M[5], Rc12 = M[9];
    const float Rc20 = M[2], Rc21 = M[6], Rc22 = M[10];
    const float cam0 = M[3], cam1 = M[7], cam2 = M[11];
    const float tc0 = -(Rc00 * cam0 + Rc01 * cam1 + Rc02 * cam2);
    const float tc1 = -(Rc10 * cam0 + Rc11 * cam1 + Rc12 * cam2);
    const float tc2 = -(Rc20 * cam0 + Rc21 * cam1 + Rc22 * cam2);
    const float fx = intr[v * 4 + 0], fy = intr[v * 4 + 1];
    const float cx = intr[v * 4 + 2], cy = intr[v * 4 + 3];

    const float X = xyz[i * 3 + 0], Y = xyz[i * 3 + 1], Z = xyz[i * 3 + 2];
    float qw = rot[i * 4 + 0], qx = rot[i * 4 + 1], qy = rot[i * 4 + 2], qz = rot[i * 4 + 3];
    {
        float qn = sqrtf(qw * qw + qx * qx + qy * qy + qz * qz);
        float inv = 1.0f / qn;
        qw *= inv; qx *= inv; qy *= inv; qz *= inv;
    }
    const float r00 = 1.f - 2.f * (qy * qy + qz * qz);
    const float r01 = 2.f * (qx * qy - qw * qz);
    const float r02 = 2.f * (qx * qz + qw * qy);
    const float r10 = 2.f * (qx * qy + qw * qz);
    const float r11 = 1.f - 2.f * (qx * qx + qz * qz);
    const float r12 = 2.f * (qy * qz - qw * qx);
    const float r20 = 2.f * (qx * qz - qw * qy);
    const float r21 = 2.f * (qy * qz + qw * qx);
    const float r22 = 1.f - 2.f * (qx * qx + qy * qy);
    const float s0 = scal[i * 3 + 0], s1 = scal[i * 3 + 1], s2 = scal[i * 3 + 2];
    const float m00 = r00 * s0, m01 = r01 * s1, m02 = r02 * s2;
    const float m10 = r10 * s0, m11 = r11 * s1, m12 = r12 * s2;
    const float m20 = r20 * s0, m21 = r21 * s1, m22 = r22 * s2;
    const float S00 = m00 * m00 + m01 * m01 + m02 * m02;
    const float S01 = m00 * m10 + m01 * m11 + m02 * m12;
    const float S02 = m00 * m20 + m01 * m21 + m02 * m22;
    const float S11 = m10 * m10 + m11 * m11 + m12 * m12;
    const float S12 = m10 * m20 + m11 * m21 + m12 * m22;
    const float S22 = m20 * m20 + m21 * m21 + m22 * m22;

    const float px = Rc00 * X + Rc01 * Y + Rc02 * Z + tc0;
    const float py = Rc10 * X + Rc11 * Y + Rc12 * Z + tc1;
    const float pz = Rc20 * X + Rc21 * Y + Rc22 * Z + tc2;
    const bool valid = pz > 0.2f;
    const float zs = fmaxf(pz, 0.2f);
    const float u  = fx * px / zs + cx;
    const float vv = fy * py / zs + cy;

    const float j00 = fx / zs;
    const float j02 = -fx * px / (zs * zs);
    const float j11 = fy / zs;
    const float j12 = -fy * py / (zs * zs);
    const float T00 = j00 * Rc00 + j02 * Rc20;
    const float T01 = j00 * Rc01 + j02 * Rc21;
    const float T02 = j00 * Rc02 + j02 * Rc22;
    const float T10 = j11 * Rc10 + j12 * Rc20;
    const float T11 = j11 * Rc11 + j12 * Rc21;
    const float T12 = j11 * Rc12 + j12 * Rc22;
    const float w0 = S00 * T00 + S01 * T01 + S02 * T02;
    const float w1 = S01 * T00 + S11 * T01 + S12 * T02;
    const float w2 = S02 * T00 + S12 * T01 + S22 * T02;
    const float a = T00 * w0 + T01 * w1 + T02 * w2 + 0.3f;
    const float b = T10 * w0 + T11 * w1 + T12 * w2;
    const float x0 = S00 * T10 + S01 * T11 + S02 * T12;
    const float x1 = S01 * T10 + S11 * T11 + S12 * T12;
    const float x2 = S02 * T10 + S12 * T11 + S22 * T12;
    const float c = T10 * x0 + T11 * x1 + T12 * x2 + 0.3f;
    const float det = fmaxf(a * c - b * b, 1e-6f);
    const float invd = 1.0f / det;
    const float ca = c * invd, cbv = -b * invd, cc = a * invd;

    float ddx = X - cam0, ddy = Y - cam1, ddz = Z - cam2;
    {
        float n = sqrtf(ddx * ddx + ddy * ddy + ddz * ddz);
        float inv = 1.0f / n;
        ddx *= inv; ddy *= inv; ddz *= inv;
    }
    float col[3];
    #pragma unroll
    for (int ch = 0; ch < 3; ++ch) {
        float f0 = feats[(i * 4 + 0) * 3 + ch];
        float f1 = feats[(i * 4 + 1) * 3 + ch];
        float f2 = feats[(i * 4 + 2) * 3 + ch];
        float f3 = feats[(i * 4 + 3) * 3 + ch];
        float cv = SH_C0 * f0 - SH_C1 * ddy * f1 + SH_C1 * ddz * f2 - SH_C1 * ddx * f3 + 0.5f;
        col[ch] = fmaxf(cv, 0.0f);
    }
    const float opv = valid ? opac[i] : 0.0f;

    unsigned int bb = 0xFFFFFFFFu;   // empty sentinel (ty0=255 never matches a row)
    if (valid && opv >= (1.0f / 255.0f)) {
        float tau = logf(255.0f * opv);
        float rx = sqrtf(fmaxf(2.0f * tau * a, 0.0f)) + 1.0f;
        float ry = sqrtf(fmaxf(2.0f * tau * c, 0.0f)) + 1.0f;
        int tx0 = (int)fmaxf(fminf(floorf((u  - rx) * 0.125f), 17.0f),  0.0f);
        int tx1 = (int)fmaxf(fminf(floorf((u  + rx) * 0.125f), 15.0f), -1.0f);
        int ty0 = (int)fmaxf(fminf(floorf((vv - ry) * 0.125f), 17.0f),  0.0f);
        int ty1 = (int)fmaxf(fminf(floorf((vv + ry) * 0.125f), 15.0f), -1.0f);
        if (tx0 <= tx1 && ty0 <= ty1)
            bb = (unsigned)tx0 | ((unsigned)tx1 << 8) | ((unsigned)ty0 << 16) | ((unsigned)ty1 << 24);
    }

    d_A[v][i]  = make_float4(u, vv, ca, cbv);
    d_B[v][i]  = make_float4(cc, opv, col[0], col[1]);
    d_b[v][i]  = col[2];
    d_BZ[v][i] = make_uint2(bb, __float_as_uint(zs));
}

__device__ __forceinline__ u64 u64min(u64 a, u64 b) { return a < b ? a : b; }
__device__ __forceinline__ u64 u64max(u64 a, u64 b) { return a > b ? a : b; }

// 2-elem/thread bitonic sort of s[0..2T) (padded with U64MAX beyond cnt).
// Active threads: tid < T (T in {128,256,512}); others only hit barriers.
template<int T>
__device__ void bitonic2(u64* s, int tid, int lane, int cnt)
{
    u64 a = U64MAX, b = U64MAX;
    if (tid < T) {
        if (tid < cnt)     a = s[tid];
        if (tid + T < cnt) b = s[tid + T];
    }
    #pragma unroll
    for (int k = 2; k <= 2 * T; k <<= 1) {
        const bool upA = ((tid & k) == 0);
        const bool upB = (((tid + T) & k) == 0);
        #pragma unroll
        for (int j = k >> 1; j > 0; j >>= 1) {
            if (j == T) {
                // in-thread exchange of pair (tid, tid+T); element tid is low side
                u64 lo = u64min(a, b), hi = u64max(a, b);
                a = upA ? lo : hi;
                b = upA ? hi : lo;
            } else if (j >= 32) {
                __syncthreads();
                if (tid < T) { s[tid] = a; s[tid + T] = b; }
                __syncthreads();
                if (tid < T) {
                    u64 pa = s[tid ^ j];
                    u64 pb = s[(tid + T) ^ j];
                    bool lowA = ((tid & j) == 0);
                    bool lowB = (((tid + T) & j) == 0);
                    a = (lowA == upA) ? u64min(a, pa) : u64max(a, pa);
                    b = (lowB == upB) ? u64min(b, pb) : u64max(b, pb);
                }
            } else {
                if (tid < T) {
                    u64 pa = __shfl_xor_sync(0xffffffffu, a, j);
                    u64 pb = __shfl_xor_sync(0xffffffffu, b, j);
                    bool low = ((lane & j) == 0);
                    a = (low == upA) ? u64min(a, pa) : u64max(a, pa);
                    b = (low == upB) ? u64min(b, pb) : u64max(b, pb);
                }
            }
        }
    }
    __syncthreads();
    if (tid < T) { s[tid] = a; s[tid + T] = b; }
    __syncthreads();
}

// One block per (row, view): gather gaussians overlapping the tile row,
// sort by (zbits, idx), write sorted list to global.
__global__ __launch_bounds__(512)
void bin_rows_kernel()
{
    __shared__ u64 s_kv[NG];
    __shared__ int s_cnt;

    const int v   = blockIdx.y;
    const int row = blockIdx.x;
    const int tid = threadIdx.x;
    const int lane = tid & 31;
    const int w    = tid >> 5;

    if (tid == 0) s_cnt = 0;
    __syncthreads();

    // scan all 1024 bboxes for row overlap (16 warps x 64 entries)
    {
        const int base0 = w * 64 + lane;
        uint2 bzq[2];
        #pragma unroll
        for (int q = 0; q < 2; ++q)
            bzq[q] = __ldg(&d_BZ[v][base0 + q * 32]);
        const unsigned int ltmask = (1u << lane) - 1u;
        #pragma unroll
        for (int q = 0; q < 2; ++q) {
            unsigned int bb = bzq[q].x;
            int ty0 = (bb >> 16) & 255, ty1 = bb >> 24;
            bool hit = (row >= ty0) & (row <= ty1);
            unsigned int bal = __ballot_sync(0xffffffffu, hit);
            int base;
            if (lane == 0) base = atomicAdd(&s_cnt, __popc(bal));
            base = __shfl_sync(0xffffffffu, base, 0);
            if (hit) {
                u64 key = ((u64)bzq[q].y << 18) |
                          ((u64)(unsigned)(base0 + q * 32) << 8) |
                          ((bb & 15u) << 4) | ((bb >> 8) & 15u);
                s_kv[base + __popc(bal & ltmask)] = key;
            }
        }
    }
    __syncthreads();
    const int cnt = s_cnt;

    // sort (uniform branch per block)
    if (cnt > 1) {
        if (cnt <= 64) {
            if (w == 0) {
                u64 a = (lane      < cnt) ? s_kv[lane]      : U64MAX;
                u64 b = (lane + 32 < cnt) ? s_kv[lane + 32] : U64MAX;
                #pragma unroll
                for (int k = 2; k <= 64; k <<= 1) {
                    const bool upA = ((lane        & k) == 0);
                    const bool upB = (((lane + 32) & k) == 0);
                    #pragma unroll
                    for (int j = k >> 1; j > 0; j >>= 1) {
                        if (j == 32) {
                            u64 lo = u64min(a, b), hi = u64max(a, b);
                            a = upA ? lo : hi;
                            b = upA ? hi : lo;
                        } else {
                            u64 pa = __shfl_xor_sync(0xffffffffu, a, j);
                            u64 pb = __shfl_xor_sync(0xffffffffu, b, j);
                            bool low = ((lane & j) == 0);
                            a = (low == upA) ? u64min(a, pa) : u64max(a, pa);
                            b = (low == upB) ? u64min(b, pb) : u64max(b, pb);
                        }
                    }
                }
                s_kv[lane]      = a;
                s_kv[lane + 32] = b;
            }
            __syncthreads();
        } else if (cnt <= 256) {
            bitonic2<128>(s_kv, tid, lane, cnt);
        } else if (cnt <= 512) {
            bitonic2<256>(s_kv, tid, lane, cnt);
        } else {
            bitonic2<512>(s_kv, tid, lane, cnt);
        }
    } else {
        __syncthreads();
    }

    for (int i2 = tid; i2 < cnt; i2 += 512)
        d_rowList[v][row][i2] = s_kv[i2];
    if (tid == 0) d_rowCnt[v][row] = cnt;
}

// Block = 512 threads: 64 pixels (8x8 tile) x 8 depth segments. No sort here.
__global__ __launch_bounds__(512)
void render_kernel(float* __restrict__ out)
{
    __shared__ u64    s_kv[NG];
    __shared__ int    s_wc[16];
    __shared__ int    s_wo[17];
    __shared__ float4 s_pa[256];
    __shared__ float4 s_pb[256];
    __shared__ float  s_pc[256];
    __shared__ float4 s_part[8][64];

    const int v    = blockIdx.y;
    const int tile = blockIdx.x;            // 0..255 -> (tile&15, tile>>4)
    const int tid  = threadIdx.x;
    const int lane = tid & 31;
    const int w    = tid >> 5;              // 0..15
    const int tx   = tile & 15;
    const int ty   = tile >> 4;

    // Phase 1: order-preserving compaction of this row's sorted list by tx range.
    const int cnt_row = d_rowCnt[v][ty];
    const u64* rl = d_rowList[v][ty];
    const int cw  = (cnt_row + 15) >> 4;         // contiguous chunk per warp
    const int beg = w * cw;
    const int end = min(beg + cw, cnt_row);

    // pass 1: count hits per warp
    int c = 0;
    for (int p0 = beg; p0 < end; p0 += 32) {
        int p = p0 + lane;
        bool hit = false;
        if (p < end) {
            u64 key = __ldg(&rl[p]);
            int t0 = (int)((key >> 4) & 15u);
            int t1 = (int)(key & 15u);
            hit = (tx >= t0) & (tx <= t1);
        }
        c += __popc(__ballot_sync(0xffffffffu, hit));
    }
    if (lane == 0) s_wc[w] = c;
    __syncthreads();
    if (tid == 0) {
        int o = 0;
        #pragma unroll
        for (int k = 0; k < 16; ++k) { s_wo[k] = o; o += s_wc[k]; }
        s_wo[16] = o;
    }
    __syncthreads();
    // pass 2: write hits in order
    {
        int run = s_wo[w];
        const unsigned int ltmask = (1u << lane) - 1u;
        for (int p0 = beg; p0 < end; p0 += 32) {
            int p = p0 + lane;
            bool hit = false;
            u64 key = 0;
            if (p < end) {
                key = __ldg(&rl[p]);
                int t0 = (int)((key >> 4) & 15u);
                int t1 = (int)(key & 15u);
                hit = (tx >= t0) & (tx <= t1);
            }
            unsigned int bal = __ballot_sync(0xffffffffu, hit);
            if (hit) s_kv[run + __popc(bal & ltmask)] = key;
            run += __popc(bal);
        }
    }
    __syncthreads();
    const int cnt = s_wo[16];

    // Phase 1c: stage payload in sorted order into shared (cnt <= 256 case).
    const bool staged = (cnt <= 256);
    if (staged) {
        for (int i2 = tid; i2 < cnt; i2 += 512) {
            const int j = (int)((s_kv[i2] >> 8) & 1023u);
            s_pa[i2] = d_A[v][j];
            s_pb[i2] = d_B[v][j];
            s_pc[i2] = d_b[v][j];
        }
        __syncthreads();
    }

    // Phase 2: 8-segment compositing.
    const int seg = tid >> 6;               // 0..7
    const int pxl = tid & 63;
    const float gx = tx * 8 + (pxl & 7) + 0.5f;
    const float gy = ty * 8 + (pxl >> 3) + 0.5f;

    const int beg2 = (cnt * seg) >> 3;
    const int end2 = (cnt * (seg + 1)) >> 3;

    float T = 1.0f, cr = 0.0f, cg = 0.0f, cb = 0.0f;
    if (staged) {
        for (int i2 = beg2; i2 < end2; ++i2) {
            float4 Ac = s_pa[i2];
            float4 Bc = s_pb[i2];
            float  Cc = s_pc[i2];
            float dx = gx - Ac.x;
            float dy = gy - Ac.y;
            float pwr = -0.5f * (Ac.z * dx * dx + Bc.x * dy * dy) - Ac.w * dx * dy;
            float al = Bc.y * __expf(pwr);
            al = fminf(al, 0.99f);
            if (pwr > 0.0f || al < (1.0f / 255.0f)) al = 0.0f;
            float wgt = al * T;
            cr = fmaf(wgt, Bc.z, cr);
            cg = fmaf(wgt, Bc.w, cg);
            cb = fmaf(wgt, Cc, cb);
            T *= (1.0f - al);
            if (__all_sync(0xffffffffu, T < 1e-5f)) break;
        }
    } else if (beg2 < end2) {
        int j0 = (int)((s_kv[beg2] >> 8) & 1023u);
        float4 A  = __ldg(&d_A[v][j0]);
        float4 B  = __ldg(&d_B[v][j0]);
        float  Cb = __ldg(&d_b[v][j0]);
        for (int i2 = beg2; i2 < end2; ++i2) {
            const float4 Ac = A;
            const float4 Bc = B;
            const float  Cc = Cb;
            if (i2 + 1 < end2) {
                int jn = (int)((s_kv[i2 + 1] >> 8) & 1023u);
                A  = __ldg(&d_A[v][jn]);
                B  = __ldg(&d_B[v][jn]);
                Cb = __ldg(&d_b[v][jn]);
            }
            float dx = gx - Ac.x;
            float dy = gy - Ac.y;
            float pwr = -0.5f * (Ac.z * dx * dx + Bc.x * dy * dy) - Ac.w * dx * dy;
            float al = Bc.y * __expf(pwr);
            al = fminf(al, 0.99f);
            if (pwr > 0.0f || al < (1.0f / 255.0f)) al = 0.0f;
            float wgt = al * T;
            cr = fmaf(wgt, Bc.z, cr);
            cg = fmaf(wgt, Bc.w, cg);
            cb = fmaf(wgt, Cc, cb);
            T *= (1.0f - al);
            if (__all_sync(0xffffffffu, T < 1e-5f)) break;
        }
    }
    s_part[seg][pxl] = make_float4(cr, cg, cb, T);
    __syncthreads();

    // Phase 3: fold 8 segments in depth order (back to front).
    if (seg == 0) {
        float4 p = s_part[7][pxl];
        float rr = p.x, gg = p.y, bbv = p.z;
        #pragma unroll
        for (int s = 6; s >= 1; --s) {
            p = s_part[s][pxl];
            rr  = fmaf(p.w, rr,  p.x);
            gg  = fmaf(p.w, gg,  p.y);
            bbv = fmaf(p.w, bbv, p.z);
        }
        rr  = fmaf(T, rr,  cr);
        gg  = fmaf(T, gg,  cg);
        bbv = fmaf(T, bbv, cb);

        const int pxi = tx * 8 + (pxl & 7);
        const int pyi = ty * 8 + (pxl >> 3);
        const int o = ((v * 3) * HW + pyi) * HW + pxi;
        out[o]               = rr;
        out[o + HW * HW]     = gg;
        out[o + 2 * HW * HW] = bbv;
    }
}

extern "C" void kernel_launch(void* const* d_in, const int* in_sizes, int n_in,
                              void* d_out, int out_size)
{
    const float* xyz   = (const float*)d_in[0];
    const float* feats = (const float*)d_in[1];
    const float* scal  = (const float*)d_in[2];
    const float* rot   = (const float*)d_in[3];
    const float* opac  = (const float*)d_in[4];

    const float* C2W  = nullptr;
    const float* intr = nullptr;
    for (int k = 5; k < n_in; ++k) {
        if (in_sizes[k] == 32 && !C2W)  C2W  = (const float*)d_in[k];
        else if (in_sizes[k] == 8 && !intr) intr = (const float*)d_in[k];
    }
    if (!C2W)  C2W  = (const float*)d_in[n_in - 2];
    if (!intr) intr = (const float*)d_in[n_in - 1];

    dim3 pgrid(NG / 128, NV);
    project_kernel<<<pgrid, 128>>>(xyz, feats, scal, rot, opac, C2W, intr);
    dim3 bgrid(NROW, NV);
    bin_rows_kernel<<<bgrid, 512>>>();
    dim3 rgrid(NT, NV);
    render_kernel<<<rgrid, 512>>>((float*)d_out);
}

// round 14
// speedup vs baseline: 1.5685x; 1.5685x over previous
#include <cuda_runtime.h>
#include <math.h>

#define NG 1024
#define NV 2
#define HW 128
#define NT 256            // 16x16 tiles of 8x8 px
#define SH_C0 0.28209479177387814f
#define SH_C1 0.4886025119029199f

typedef unsigned long long u64;
#define U64MAX 0xFFFFFFFFFFFFFFFFull

// Per-gaussian payload in ORIGINAL index order:
// A = (u, v, conic_a, conic_b); B = (conic_c, opacity, colR, colG); b = colB
// BZ.x = tile coverage masks: colmask (bits 0..15) | rowmask<<16; BZ.y = camera-z bits
__device__ float4 d_A[NV][NG], d_B[NV][NG];
__device__ float  d_b[NV][NG];
__device__ uint2  d_BZ[NV][NG];

__global__ __launch_bounds__(128)
void project_kernel(const float* __restrict__ xyz,
                    const float* __restrict__ feats,
                    const float* __restrict__ scal,
                    const float* __restrict__ rot,
                    const float* __restrict__ opac,
                    const float* __restrict__ C2W,
                    const float* __restrict__ intr)
{
    const int v = blockIdx.y;
    const int i = blockIdx.x * 128 + threadIdx.x;

    const float* M = C2W + v * 16;
    const float Rc00 = M[0], Rc01 = M[4], Rc02 = M[8];
    const float Rc10 = M[1], Rc11 = M[5], Rc12 = M[9];
    const float Rc20 = M[2], Rc21 = M[6], Rc22 = M[10];
    const float cam0 = M[3], cam1 = M[7], cam2 = M[11];
    const float tc0 = -(Rc00 * cam0 + Rc01 * cam1 + Rc02 * cam2);
    const float tc1 = -(Rc10 * cam0 + Rc11 * cam1 + Rc12 * cam2);
    const float tc2 = -(Rc20 * cam0 + Rc21 * cam1 + Rc22 * cam2);
    const float fx = intr[v * 4 + 0], fy = intr[v * 4 + 1];
    const float cx = intr[v * 4 + 2], cy = intr[v * 4 + 3];

    const float X = xyz[i * 3 + 0], Y = xyz[i * 3 + 1], Z = xyz[i * 3 + 2];
    float qw = rot[i * 4 + 0], qx = rot[i * 4 + 1], qy = rot[i * 4 + 2], qz = rot[i * 4 + 3];
    {
        float qn = sqrtf(qw * qw + qx * qx + qy * qy + qz * qz);
        float inv = 1.0f / qn;
        qw *= inv; qx *= inv; qy *= inv; qz *= inv;
    }
    const float r00 = 1.f - 2.f * (qy * qy + qz * qz);
    const float r01 = 2.f * (qx * qy - qw * qz);
    const float r02 = 2.f * (qx * qz + qw * qy);
    const float r10 = 2.f * (qx * qy + qw * qz);
    const float r11 = 1.f - 2.f * (qx * qx + qz * qz);
    const float r12 = 2.f * (qy * qz - qw * qx);
    const float r20 = 2.f * (qx * qz - qw * qy);
    const float r21 = 2.f * (qy * qz + qw * qx);
    const float r22 = 1.f - 2.f * (qx * qx + qy * qy);
    const float s0 = scal[i * 3 + 0], s1 = scal[i * 3 + 1], s2 = scal[i * 3 + 2];
    const float m00 = r00 * s0, m01 = r01 * s1, m02 = r02 * s2;
    const float m10 = r10 * s0, m11 = r11 * s1, m12 = r12 * s2;
    const float m20 = r20 * s0, m21 = r21 * s1, m22 = r22 * s2;
    const float S00 = m00 * m00 + m01 * m01 + m02 * m02;
    const float S01 = m00 * m10 + m01 * m11 + m02 * m12;
    const float S02 = m00 * m20 + m01 * m21 + m02 * m22;
    const float S11 = m10 * m10 + m11 * m11 + m12 * m12;
    const float S12 = m10 * m20 + m11 * m21 + m12 * m22;
    const float S22 = m20 * m20 + m21 * m21 + m22 * m22;

    const float px = Rc00 * X + Rc01 * Y + Rc02 * Z + tc0;
    const float py = Rc10 * X + Rc11 * Y + Rc12 * Z + tc1;
    const float pz = Rc20 * X + Rc21 * Y + Rc22 * Z + tc2;
    const bool valid = pz > 0.2f;
    const float zs = fmaxf(pz, 0.2f);
    const float u  = fx * px / zs + cx;
    const float vv = fy * py / zs + cy;

    const float j00 = fx / zs;
    const float j02 = -fx * px / (zs * zs);
    const float j11 = fy / zs;
    const float j12 = -fy * py / (zs * zs);
    const float T00 = j00 * Rc00 + j02 * Rc20;
    const float T01 = j00 * Rc01 + j02 * Rc21;
    const float T02 = j00 * Rc02 + j02 * Rc22;
    const float T10 = j11 * Rc10 + j12 * Rc20;
    const float T11 = j11 * Rc11 + j12 * Rc21;
    const float T12 = j11 * Rc12 + j12 * Rc22;
    const float w0 = S00 * T00 + S01 * T01 + S02 * T02;
    const float w1 = S01 * T00 + S11 * T01 + S12 * T02;
    const float w2 = S02 * T00 + S12 * T01 + S22 * T02;
    const float a = T00 * w0 + T01 * w1 + T02 * w2 + 0.3f;
    const float b = T10 * w0 + T11 * w1 + T12 * w2;
    const float x0 = S00 * T10 + S01 * T11 + S02 * T12;
    const float x1 = S01 * T10 + S11 * T11 + S12 * T12;
    const float x2 = S02 * T10 + S12 * T11 + S22 * T12;
    const float c = T10 * x0 + T11 * x1 + T12 * x2 + 0.3f;
    const float det = fmaxf(a * c - b * b, 1e-6f);
    const float invd = 1.0f / det;
    const float ca = c * invd, cbv = -b * invd, cc = a * invd;

    float ddx = X - cam0, ddy = Y - cam1, ddz = Z - cam2;
    {
        float n = sqrtf(ddx * ddx + ddy * ddy + ddz * ddz);
        float inv = 1.0f / n;
        ddx *= inv; ddy *= inv; ddz *= inv;
    }
    float col[3];
    #pragma unroll
    for (int ch = 0; ch < 3; ++ch) {
        float f0 = feats[(i * 4 + 0) * 3 + ch];
        float f1 = feats[(i * 4 + 1) * 3 + ch];
        float f2 = feats[(i * 4 + 2) * 3 + ch];
        float f3 = feats[(i * 4 + 3) * 3 + ch];
        float cv = SH_C0 * f0 - SH_C1 * ddy * f1 + SH_C1 * ddz * f2 - SH_C1 * ddx * f3 + 0.5f;
        col[ch] = fmaxf(cv, 0.0f);
    }
    const float opv = valid ? opac[i] : 0.0f;

    unsigned int bb = 0u;   // empty = no coverage
    if (valid && opv >= (1.0f / 255.0f)) {
        float tau = logf(255.0f * opv);
        float rx = sqrtf(fmaxf(2.0f * tau * a, 0.0f)) + 1.0f;
        float ry = sqrtf(fmaxf(2.0f * tau * c, 0.0f)) + 1.0f;
        int tx0 = (int)fmaxf(fminf(floorf((u  - rx) * 0.125f), 17.0f),  0.0f);
        int tx1 = (int)fmaxf(fminf(floorf((u  + rx) * 0.125f), 15.0f), -1.0f);
        int ty0 = (int)fmaxf(fminf(floorf((vv - ry) * 0.125f), 17.0f),  0.0f);
        int ty1 = (int)fmaxf(fminf(floorf((vv + ry) * 0.125f), 15.0f), -1.0f);
        if (tx0 <= tx1 && ty0 <= ty1) {
            unsigned colm = (0xFFFFu << tx0) & (0xFFFFu >> (15 - tx1));
            unsigned rowm = (0xFFFFu << ty0) & (0xFFFFu >> (15 - ty1));
            bb = colm | (rowm << 16);
        }
    }

    d_A[v][i]  = make_float4(u, vv, ca, cbv);
    d_B[v][i]  = make_float4(cc, opv, col[0], col[1]);
    d_b[v][i]  = col[2];
    d_BZ[v][i] = make_uint2(bb, __float_as_uint(zs));
}

// Block = 512 threads: 64 pixels (8x8 tile) x 8 depth segments.
__global__ __launch_bounds__(512)
void render_kernel(float* __restrict__ out)
{
    __shared__ u64    s_kv[NG];
    __shared__ int    s_cnt;
    __shared__ float4 s_pa[256];
    __shared__ float4 s_pb[256];
    __shared__ float  s_pc[256];
    __shared__ float4 s_part[8][64];

    const int v    = blockIdx.y;
    const int tile = blockIdx.x;            // 0..255 -> (tile&15, tile>>4)
    const int tid  = threadIdx.x;
    const int lane = tid & 31;
    const int w    = tid >> 5;              // 0..15
    const int tx   = tile & 15;
    const int ty   = tile >> 4;
    const int tysh = ty + 16;

    if (tid == 0) s_cnt = 0;
    __syncthreads();

    // Phase 1: 16 warps scan 1024 (mask,z) pairs; 2-instruction hit test;
    // ballot-compact (atomic + shfl skipped when ballot is empty).
    {
        const int base0 = w * 64 + lane;
        uint2 bzq[2];
        #pragma unroll
        for (int q = 0; q < 2; ++q)
            bzq[q] = __ldg(&d_BZ[v][base0 + q * 32]);
        const unsigned int ltmask = (1u << lane) - 1u;
        #pragma unroll
        for (int q = 0; q < 2; ++q) {
            const unsigned int bb = bzq[q].x;
            bool hit = ((bb >> tx) & (bb >> tysh) & 1u) != 0u;
            unsigned int bal = __ballot_sync(0xffffffffu, hit);
            if (bal) {
                int base;
                if (lane == 0) base = atomicAdd(&s_cnt, __popc(bal));
                base = __shfl_sync(0xffffffffu, base, 0);
                if (hit)
                    s_kv[base + __popc(bal & ltmask)] =
                        ((u64)bzq[q].y << 32) | (unsigned)(base0 + q * 32);
            }
        }
    }
    __syncthreads();
    const int cnt = s_cnt;

    // Phase 1b: sort tile list by (zbits, idx) ascending. Branches are uniform.
    if (cnt > 64 && cnt <= 256) {
        u64 val = (tid < 256 && tid < cnt) ? s_kv[tid] : U64MAX;
        #pragma unroll
        for (int k = 2; k <= 256; k <<= 1) {
            const bool up = ((tid & k) == 0);
            for (int j = k >> 1; j > 0; j >>= 1) {
                bool keepmin = (((tid & j) == 0) == up);
                u64 p;
                if (j >= 32) {
                    if (tid < 256) s_kv[tid] = val;
                    __syncthreads();
                    p = (tid < 256) ? s_kv[tid ^ j] : U64MAX;
                    __syncthreads();
                } else {
                    p = __shfl_xor_sync(0xffffffffu, val, j);
                }
                val = keepmin ? (val < p ? val : p) : (val > p ? val : p);
            }
        }
        if (tid < 256) s_kv[tid] = val;
        __syncthreads();
    } else if (cnt > 1 && cnt <= 64) {
        if (w == 0) {
            u64 a = (lane      < cnt) ? s_kv[lane]      : U64MAX;
            u64 b = (lane + 32 < cnt) ? s_kv[lane + 32] : U64MAX;
            #pragma unroll
            for (int k = 2; k <= 64; k <<= 1) {
                const bool upA = ((lane        & k) == 0);
                const bool upB = (((lane + 32) & k) == 0);
                #pragma unroll
                for (int j = k >> 1; j > 0; j >>= 1) {
                    if (j == 32) {
                        u64 lo = a < b ? a : b;
                        u64 hi = a < b ? b : a;
                        a = upA ? lo : hi;
                        b = upA ? hi : lo;
                    } else {
                        u64 pa = __shfl_xor_sync(0xffffffffu, a, j);
                        u64 pb = __shfl_xor_sync(0xffffffffu, b, j);
                        bool low = ((lane & j) == 0);
                        a = (low == upA) ? (a < pa ? a : pa) : (a > pa ? a : pa);
                        b = (low == upB) ? (b < pb ? b : pb) : (b > pb ? b : pb);
                    }
                }
            }
            s_kv[lane]      = a;
            s_kv[lane + 32] = b;
        }
        __syncthreads();
    } else if (cnt > 256) {
        int m = 2;
        while (m < cnt) m <<= 1;
        for (int t = cnt + tid; t < m; t += 512) s_kv[t] = U64MAX;
        __syncthreads();
        for (int k = 2; k <= m; k <<= 1) {
            for (int j = k >> 1; j > 0; j >>= 1) {
                for (int p = tid; p < (m >> 1); p += 512) {
                    int lo = ((p & ~(j - 1)) << 1) | (p & (j - 1));
                    int hi = lo | j;
                    u64 x = s_kv[lo], y = s_kv[hi];
                    bool up = ((lo & k) == 0);
                    if ((x > y) == up) { s_kv[lo] = y; s_kv[hi] = x; }
                }
                __syncthreads();
            }
        }
    } else {
        __syncthreads();
    }

    // Phase 1c: stage payload in sorted order into shared (cnt <= 256 case).
    const bool staged = (cnt <= 256);
    if (staged) {
        for (int i2 = tid; i2 < cnt; i2 += 512) {
            const int j = (int)(s_kv[i2] & 1023u);
            s_pa[i2] = d_A[v][j];
            s_pb[i2] = d_B[v][j];
            s_pc[i2] = d_b[v][j];
        }
        __syncthreads();
    }

    // Phase 2: 8-segment compositing.
    const int seg = tid >> 6;               // 0..7
    const int pxl = tid & 63;
    const float gx = tx * 8 + (pxl & 7) + 0.5f;
    const float gy = ty * 8 + (pxl >> 3) + 0.5f;

    const int beg = (cnt * seg) >> 3;
    const int end = (cnt * (seg + 1)) >> 3;

    float T = 1.0f, cr = 0.0f, cg = 0.0f, cb = 0.0f;
    if (staged) {
        for (int i2 = beg; i2 < end; ++i2) {
            float4 Ac = s_pa[i2];
            float4 Bc = s_pb[i2];
            float  Cc = s_pc[i2];
            float dx = gx - Ac.x;
            float dy = gy - Ac.y;
            float pwr = -0.5f * (Ac.z * dx * dx + Bc.x * dy * dy) - Ac.w * dx * dy;
            float al = Bc.y * __expf(pwr);
            al = fminf(al, 0.99f);
            if (pwr > 0.0f || al < (1.0f / 255.0f)) al = 0.0f;
            float wgt = al * T;
            cr = fmaf(wgt, Bc.z, cr);
            cg = fmaf(wgt, Bc.w, cg);
            cb = fmaf(wgt, Cc, cb);
            T *= (1.0f - al);
            if (__all_sync(0xffffffffu, T < 1e-5f)) break;
        }
    } else if (beg < end) {
        int j0 = (int)(s_kv[beg] & 1023u);
        float4 A  = __ldg(&d_A[v][j0]);
        float4 B  = __ldg(&d_B[v][j0]);
        float  Cb = __ldg(&d_b[v][j0]);
        for (int i2 = beg; i2 < end; ++i2) {
            const float4 Ac = A;
            const float4 Bc = B;
            const float  Cc = Cb;
            if (i2 + 1 < end) {
                int jn = (int)(s_kv[i2 + 1] & 1023u);
                A  = __ldg(&d_A[v][jn]);
                B  = __ldg(&d_B[v][jn]);
                Cb = __ldg(&d_b[v][jn]);
            }
            float dx = gx - Ac.x;
            float dy = gy - Ac.y;
            float pwr = -0.5f * (Ac.z * dx * dx + Bc.x * dy * dy) - Ac.w * dx * dy;
            float al = Bc.y * __expf(pwr);
            al = fminf(al, 0.99f);
            if (pwr > 0.0f || al < (1.0f / 255.0f)) al = 0.0f;
            float wgt = al * T;
            cr = fmaf(wgt, Bc.z, cr);
            cg = fmaf(wgt, Bc.w, cg);
            cb = fmaf(wgt, Cc, cb);
            T *= (1.0f - al);
            if (__all_sync(0xffffffffu, T < 1e-5f)) break;
        }
    }
    s_part[seg][pxl] = make_float4(cr, cg, cb, T);
    __syncthreads();

    // Phase 3: fold 8 segments in depth order (back to front).
    if (seg == 0) {
        float4 p = s_part[7][pxl];
        float rr = p.x, gg = p.y, bbv = p.z;
        #pragma unroll
        for (int s = 6; s >= 1; --s) {
            p = s_part[s][pxl];
            rr  = fmaf(p.w, rr,  p.x);
            gg  = fmaf(p.w, gg,  p.y);
            bbv = fmaf(p.w, bbv, p.z);
        }
        rr  = fmaf(T, rr,  cr);
        gg  = fmaf(T, gg,  cg);
        bbv = fmaf(T, bbv, cb);

        const int pxi = tx * 8 + (pxl & 7);
        const int pyi = ty * 8 + (pxl >> 3);
        const int o = ((v * 3) * HW + pyi) * HW + pxi;
        out[o]               = rr;
        out[o + HW * HW]     = gg;
        out[o + 2 * HW * HW] = bbv;
    }
}

extern "C" void kernel_launch(void* const* d_in, const int* in_sizes, int n_in,
                              void* d_out, int out_size)
{
    const float* xyz   = (const float*)d_in[0];
    const float* feats = (const float*)d_in[1];
    const float* scal  = (const float*)d_in[2];
    const float* rot   = (const float*)d_in[3];
    const float* opac  = (const float*)d_in[4];

    const float* C2W  = nullptr;
    const float* intr = nullptr;
    for (int k = 5; k < n_in; ++k) {
        if (in_sizes[k] == 32 && !C2W)  C2W  = (const float*)d_in[k];
        else if (in_sizes[k] == 8 && !intr) intr = (const float*)d_in[k];
    }
    if (!C2W)  C2W  = (const float*)d_in[n_in - 2];
    if (!intr) intr = (const float*)d_in[n_in - 1];

    dim3 pgrid(NG / 128, NV);
    project_kernel<<<pgrid, 128>>>(xyz, feats, scal, rot, opac, C2W, intr);
    dim3 rgrid(NT, NV);
    render_kernel<<<rgrid, 512>>>((float*)d_out);
}